// round 11
// baseline (speedup 1.0000x reference)
#include <cuda_runtime.h>

// SNN forward: B=128, T=1000, F=20, H=256, O=200.
// 1 CTA per batch element, 1024 threads, persistent loop.
// LAYER-PIPELINED: iteration t -> layer1 step t, layer2 step t-1, readout t-2.
// Single gather phase (V1/W2T/V2/WoT concurrent, int4 list blocks, f32x2 adds)
// + 2 full barriers. R11: softmax DEFERRED to a post-kernel; the in-loop readout
// only updates synO/memO/spkO and streams memO to global scratch.

#define Bt 128
#define Tt 1000
#define Ft 20
#define Ht 256
#define Ot 200
#define NTHR 1024
#define ZID 256                 // id of the all-zero padding row

// Preprocessed weights, 257 rows (row 256 = zeros), L2-resident (~1MB).
__device__ __align__(16) float g_V1[257 * 256];
__device__ __align__(16) float g_V2[257 * 256];
__device__ __align__(16) float g_W2T[257 * 256];   // W2T[h][g] = W2[g][h]
__device__ __align__(16) float g_WoT[257 * 200];   // WoT[h][o] = Wout[o][h]
__device__ float g_memO[(size_t)Tt * Bt * Ot];     // memO(tau) series for deferred softmax

__global__ void snn_prep(const float* __restrict__ V1, const float* __restrict__ V2,
                         const float* __restrict__ W2, const float* __restrict__ Wout) {
    int i = blockIdx.x * blockDim.x + threadIdx.x;
    if (i < 257 * 256) {
        int r = i >> 8, c = i & 255;
        if (r < 256) {
            float z = (r == c) ? 0.0f : 1.0f;
            g_V1[i]  = V1[r * 256 + c] * z;
            g_V2[i]  = V2[r * 256 + c] * z;
            g_W2T[i] = W2[c * 256 + r];
        } else {
            g_V1[i] = 0.f; g_V2[i] = 0.f; g_W2T[i] = 0.f;
        }
    }
    if (i < 257 * 200) {
        int h = i / 200, o = i - h * 200;
        g_WoT[i] = (h < 256) ? Wout[o * 256 + h] : 0.f;
    }
}

// Dynamic SMEM layout (float index):
#define OFF_W1T  0        // [5120]  W1 transposed [F][H]
#define OFF_PA   5120     // [4*256] V1  partials
#define OFF_PC   6144     // [4*256] W2T partials
#define OFF_PB   7168     // [4*256] V2  partials
#define OFF_PW   8192     // [4*256] WoT partials
#define OFF_L1   9216     // [2*260] int: ping-pong padded spike list layer1
#define OFF_L2   9736     // [2*260] int: ping-pong padded spike list layer2
#define OFF_WC1  10256    // [8]   int
#define OFF_WC2  10264    // [8]   int
#define OFF_NCNT 10272    // [4]   int: n1[2], n2[2]
#define OFF_XBUF 10276    // [2*20] x(t) double buffer
#define SMEM_FLOATS (10276 + 40)
#define SMEM_BYTES  (SMEM_FLOATS * 4)

#define NB1() asm volatile("bar.sync 1, 256;" ::: "memory")   // warps 0-7   (layer1)
#define NB2() asm volatile("bar.sync 3, 256;" ::: "memory")   // warps 8-15  (layer2)
#define ADDX2(d, a, b) asm("add.rn.f32x2 %0, %1, %2;" : "=l"(d) : "l"(a), "l"(b))

// Gather 4 consecutive ids (one int4 block) from `base` rows of `stride` floats.
#define GATHER4(ptr, stride)                                                    \
    do {                                                                        \
        ulonglong2 v0 = __ldg((const ulonglong2*)((ptr) + e.x * (stride)));     \
        ulonglong2 v1 = __ldg((const ulonglong2*)((ptr) + e.y * (stride)));     \
        ulonglong2 v2 = __ldg((const ulonglong2*)((ptr) + e.z * (stride)));     \
        ulonglong2 v3 = __ldg((const ulonglong2*)((ptr) + e.w * (stride)));     \
        ADDX2(s0, s0, v0.x); ADDX2(s1, s1, v0.y);                               \
        ADDX2(s2, s2, v1.x); ADDX2(s3, s3, v1.y);                               \
        ADDX2(s0, s0, v2.x); ADDX2(s1, s1, v2.y);                               \
        ADDX2(s2, s2, v3.x); ADDX2(s3, s3, v3.y);                               \
    } while (0)

__global__ __launch_bounds__(NTHR, 1)
void snn_main(const float* __restrict__ x, const float* __restrict__ W1,
              const float* __restrict__ b1, const float* __restrict__ beta1,
              const float* __restrict__ b2, const float* __restrict__ beta2,
              const float* __restrict__ alpha_out, const float* __restrict__ beta_out) {
    extern __shared__ float sm[];
    float* w1t  = sm + OFF_W1T;
    float* PA   = sm + OFF_PA;
    float* PC   = sm + OFF_PC;
    float* PB   = sm + OFF_PB;
    float* PW   = sm + OFF_PW;
    int*   l1   = (int*)(sm + OFF_L1);
    int*   l2   = (int*)(sm + OFF_L2);
    int*   wc1  = (int*)(sm + OFF_WC1);
    int*   wc2  = (int*)(sm + OFF_WC2);
    int*   ncnt = (int*)(sm + OFF_NCNT);
    float* xbuf = sm + OFF_XBUF;

    const int tid  = threadIdx.x;
    const int b    = blockIdx.x;
    const int grp  = tid >> 6;              // 0..15 (64-thread row groups)
    const int g    = grp & 3;               // group within matrix
    const int mat  = grp >> 2;              // 0:V1 1:W2T 2:V2 3:WoT
    const int lg   = tid & 63;              // float4 column within row
    const int wid  = tid >> 5, lane = tid & 31;
    const float* xb = x + (size_t)b * (Tt * Ft);

    for (int i = tid; i < Ft * Ht; i += NTHR) {       // W1^T [F][H]
        int f = i >> 8, h = i & 255;
        w1t[i] = W1[h * Ft + f];
    }
    if (tid < 4) ncnt[tid] = 0;
    if (tid < Ft) xbuf[tid] = __ldg(xb + tid);        // x(0) -> slot 0

    // Role state: layer1 on tid 0-255, layer2 on 256-511, readout on 768-967
    // (the WoT gather band itself -> PW producer == consumer).
    float syn1 = 0.f, mem1 = 0.f, spk1 = 0.f;
    float syn2 = 0.f, mem2 = 0.f, spk2 = 0.f;
    float synO = 0.f, memO = 0.f, spkO = 0.f;
    float b1r = 0.f, be1 = 0.f, b2r = 0.f, be2 = 0.f, aOr = 0.f, bOr = 0.f;
    const int h2 = tid - 256;                         // layer2 neuron index
    const int oo = tid - 768;                         // output neuron index (band 3)
    if (tid < Ht)              { b1r = b1[tid]; be1 = beta1[tid]; }
    if (h2 >= 0 && h2 < Ht)    { b2r = b2[h2];  be2 = beta2[h2]; }
    if (oo >= 0 && oo < Ot)    { aOr = alpha_out[oo]; bOr = beta_out[oo]; }
    __syncthreads();

    // Iteration t: layer1 step t (t<Tt), layer2 step t-1 (1<=t<=Tt),
    // readout step t-2 (2<=t<=Tt+1). Gathers read parity q, updates write p.
    for (int t = 0; t <= Tt + 1; t++) {
        const int p = t & 1, q = p ^ 1;
        const int nB1o = (ncnt[q] + 3) >> 2;      // int4 blocks in l1[q]
        const int nB2o = (ncnt[2 + q] + 3) >> 2;  // int4 blocks in l2[q]

        float xnext = 0.f;
        if (tid < Ft && t + 1 < Tt) xnext = __ldg(xb + (t + 1) * Ft + tid);

        // ---- single gather phase: 4 matrices concurrently, int4 list blocks ----
        if (mat == 0) {               // V1 rows over l1[q] -> PA
            if (t < Tt) {
                const float* base = g_V1 + 4 * lg;
                const int4* lst4 = (const int4*)(l1 + q * 260);
                unsigned long long s0 = 0ull, s1 = 0ull, s2 = 0ull, s3 = 0ull;
                #pragma unroll 2
                for (int k = g; k < nB1o; k += 4) {
                    int4 e = lst4[k];
                    GATHER4(base, 256);
                }
                ulonglong2 r; ADDX2(r.x, s0, s2); ADDX2(r.y, s1, s3);
                *(ulonglong2*)(PA + g * 256 + 4 * lg) = r;
            }
        } else if (mat == 1) {        // W2T rows over l1[q] -> PC
            if (t >= 1 && t <= Tt) {
                const float* base = g_W2T + 4 * lg;
                const int4* lst4 = (const int4*)(l1 + q * 260);
                unsigned long long s0 = 0ull, s1 = 0ull, s2 = 0ull, s3 = 0ull;
                #pragma unroll 2
                for (int k = g; k < nB1o; k += 4) {
                    int4 e = lst4[k];
                    GATHER4(base, 256);
                }
                ulonglong2 r; ADDX2(r.x, s0, s2); ADDX2(r.y, s1, s3);
                *(ulonglong2*)(PC + g * 256 + 4 * lg) = r;
            }
        } else if (mat == 2) {        // V2 rows over l2[q] -> PB
            if (t >= 1 && t <= Tt) {
                const float* base = g_V2 + 4 * lg;
                const int4* lst4 = (const int4*)(l2 + q * 260);
                unsigned long long s0 = 0ull, s1 = 0ull, s2 = 0ull, s3 = 0ull;
                #pragma unroll 2
                for (int k = g; k < nB2o; k += 4) {
                    int4 e = lst4[k];
                    GATHER4(base, 256);
                }
                ulonglong2 r; ADDX2(r.x, s0, s2); ADDX2(r.y, s1, s3);
                *(ulonglong2*)(PB + g * 256 + 4 * lg) = r;
            }
        } else {                      // WoT rows (200 wide) over l2[q] -> PW
            if (t >= 2 && lg < 50) {
                const float* base = g_WoT + 4 * lg;
                const int4* lst4 = (const int4*)(l2 + q * 260);
                unsigned long long s0 = 0ull, s1 = 0ull, s2 = 0ull, s3 = 0ull;
                #pragma unroll 2
                for (int k = g; k < nB2o; k += 4) {
                    int4 e = lst4[k];
                    GATHER4(base, 200);
                }
                ulonglong2 r; ADDX2(r.x, s0, s2); ADDX2(r.y, s1, s3);
                *(ulonglong2*)(PW + g * 256 + 4 * lg) = r;
            }
        }
        __syncthreads();                                        // S1
        if (tid < Ft && t + 1 < Tt) xbuf[q * Ft + tid] = xnext;

        // ---- layer1 step t (warps 0-7) ----
        if (t < Tt && tid < Ht) {
            const float* xt = xbuf + p * Ft;
            float a0 = b1r, a1 = 0.f, a2 = 0.f, a3 = 0.f;
            #pragma unroll
            for (int f = 0; f < 5; f++) {
                a0 = fmaf(xt[f],      w1t[f * Ht + tid],        a0);
                a1 = fmaf(xt[f + 5],  w1t[(f + 5) * Ht + tid],  a1);
                a2 = fmaf(xt[f + 10], w1t[(f + 10) * Ht + tid], a2);
                a3 = fmaf(xt[f + 15], w1t[(f + 15) * Ht + tid], a3);
            }
            float wx = (a0 + a1) + (a2 + a3);
            float s = ((PA[tid] + PA[256 + tid]) + (PA[512 + tid] + PA[768 + tid]));
            syn1 = 0.95f * syn1 + (wx + s);
            mem1 = be1 * mem1 + syn1 - spk1;                    // THR=1, detached reset
            spk1 = (mem1 - 1.0f) > 0.f ? 1.f : 0.f;

            unsigned bal = __ballot_sync(0xffffffffu, spk1 != 0.f);
            if (lane == 0) wc1[wid] = __popc(bal);
            NB1();
            int off = 0, tot = 0;
            #pragma unroll
            for (int w = 0; w < 8; w++) { int c = wc1[w]; off += (w < wid) ? c : 0; tot += c; }
            if (spk1 != 0.f) l1[p * 260 + off + __popc(bal & ((1u << lane) - 1u))] = tid;
            if (tid >= tot && tid < tot + 4) l1[p * 260 + tid] = ZID;  // pad block
            if (tid == 0) ncnt[p] = tot;
        }

        // ---- layer2 step t-1 (warps 8-15) ----
        if (t >= 1 && t <= Tt && h2 >= 0 && h2 < Ht) {
            const int w2 = wid - 8;
            float s = ((PC[h2] + PC[256 + h2]) + (PC[512 + h2] + PC[768 + h2])) +
                      ((PB[h2] + PB[256 + h2]) + (PB[512 + h2] + PB[768 + h2]));
            syn2 = 0.95f * syn2 + (b2r + s);
            mem2 = be2 * mem2 + syn2 - spk2;
            spk2 = (mem2 - 1.0f) > 0.f ? 1.f : 0.f;

            unsigned bal = __ballot_sync(0xffffffffu, spk2 != 0.f);
            if (lane == 0) wc2[w2] = __popc(bal);
            NB2();
            int off = 0, tot = 0;
            #pragma unroll
            for (int w = 0; w < 8; w++) { int c = wc2[w]; off += (w < w2) ? c : 0; tot += c; }
            if (spk2 != 0.f) l2[p * 260 + off + __popc(bal & ((1u << lane) - 1u))] = h2;
            if (h2 >= tot && h2 < tot + 4) l2[p * 260 + h2] = ZID;    // pad block
            if (h2 == 0) ncnt[2 + p] = tot;
        }

        // ---- readout step t-2 (band 3, warps 24-31): state update + stream memO ----
        if (t >= 2 && oo >= 0 && oo < Ot) {
            float o_t = ((PW[oo] + PW[256 + oo]) + (PW[512 + oo] + PW[768 + oo]));
            synO = aOr * synO + o_t;
            memO = bOr * memO + synO - spkO;
            spkO = (memO - 1.0f) > 0.f ? 1.f : 0.f;
            g_memO[((size_t)(t - 2) * Bt + b) * Ot + oo] = memO;
        }
        __syncthreads();                                        // S2
    }
}

// out zeroing (d_out poisoned by harness).
__global__ __launch_bounds__(256) void snn_zero(float* __restrict__ out) {
    int i = blockIdx.x * blockDim.x + threadIdx.x;
    if (i < Bt * Ot) out[i] = 0.f;
}

// Deferred softmax + warmup-masked accumulate. Grid: 128 b x 8 chunks.
__global__ __launch_bounds__(256) void snn_soft(float* __restrict__ out) {
    __shared__ float redm[8], reds[8];
    const int bb = blockIdx.x >> 3, ch = blockIdx.x & 7;
    const int tid = threadIdx.x, wd = tid >> 5, ln = tid & 31;
    int t0 = ch * 125; if (t0 < 11) t0 = 11;     // step > WARMUP(10)
    const int t1 = (ch + 1) * 125;
    float acc = 0.f;
    for (int tau = t0; tau < t1; tau++) {
        float m = (tid < Ot) ? g_memO[((size_t)tau * Bt + bb) * Ot + tid] : -3.402823e38f;
        float mv = m;
        #pragma unroll
        for (int s = 16; s; s >>= 1) mv = fmaxf(mv, __shfl_xor_sync(0xffffffffu, mv, s));
        if (ln == 0) redm[wd] = mv;
        __syncthreads();
        float mx = fmaxf(fmaxf(fmaxf(redm[0], redm[1]), fmaxf(redm[2], redm[3])),
                         fmaxf(fmaxf(redm[4], redm[5]), fmaxf(redm[6], redm[7])));
        float ev = (tid < Ot) ? __expf(m - mx) : 0.f;
        float sv = ev;
        #pragma unroll
        for (int s = 16; s; s >>= 1) sv += __shfl_xor_sync(0xffffffffu, sv, s);
        if (ln == 0) reds[wd] = sv;
        __syncthreads();
        float ssum = (((reds[0] + reds[1]) + (reds[2] + reds[3])) +
                      ((reds[4] + reds[5]) + (reds[6] + reds[7])));
        acc += ev / ssum;
    }
    if (tid < Ot) atomicAdd(&out[bb * Ot + tid], acc);
}

extern "C" void kernel_launch(void* const* d_in, const int* in_sizes, int n_in,
                              void* d_out, int out_size) {
    const float* x         = (const float*)d_in[0];
    const float* W1        = (const float*)d_in[1];
    const float* b1        = (const float*)d_in[2];
    const float* Vrec1     = (const float*)d_in[3];
    const float* beta1     = (const float*)d_in[4];
    const float* W2        = (const float*)d_in[5];
    const float* b2        = (const float*)d_in[6];
    const float* Vrec2     = (const float*)d_in[7];
    const float* beta2     = (const float*)d_in[8];
    const float* Wout      = (const float*)d_in[9];
    const float* alpha_out = (const float*)d_in[10];
    const float* beta_out  = (const float*)d_in[11];
    float* out = (float*)d_out;

    cudaFuncSetAttribute((const void*)snn_main,
                         cudaFuncAttributeMaxDynamicSharedMemorySize, SMEM_BYTES);

    snn_prep<<<(257 * 256 + 255) / 256, 256>>>(Vrec1, Vrec2, W2, Wout);
    snn_main<<<Bt, NTHR, SMEM_BYTES>>>(x, W1, b1, beta1, b2, beta2,
                                       alpha_out, beta_out);
    snn_zero<<<(Bt * Ot + 255) / 256, 256>>>(out);
    snn_soft<<<Bt * 8, 256>>>(out);
}

// round 12
// speedup vs baseline: 1.0408x; 1.0408x over previous
#include <cuda_runtime.h>

// SNN forward: B=128, T=1000, F=20, H=256, O=200.
// snn_main: 1 CTA per batch element, 1024 threads, layer-pipelined persistent loop
// (layer1 step t, layer2 step t-1, readout state t-2), single gather phase
// (V1/W2T/V2/WoT concurrent, int4 list blocks, f32x2 adds) + 2 full barriers.
// Softmax DEFERRED: main streams memO; snn_soft (warp-per-(b,chunk)) reduces it.

#define Bt 128
#define Tt 1000
#define Ft 20
#define Ht 256
#define Ot 200
#define NTHR 1024
#define ZID 256                 // id of the all-zero padding row

// Preprocessed weights, 257 rows (row 256 = zeros), L2-resident (~1MB).
__device__ __align__(16) float g_V1[257 * 256];
__device__ __align__(16) float g_V2[257 * 256];
__device__ __align__(16) float g_W2T[257 * 256];   // W2T[h][g] = W2[g][h]
__device__ __align__(16) float g_WoT[257 * 200];   // WoT[h][o] = Wout[o][h]
__device__ float g_memO[(size_t)Tt * Bt * Ot];     // memO(tau) series for deferred softmax

__global__ void snn_prep(const float* __restrict__ V1, const float* __restrict__ V2,
                         const float* __restrict__ W2, const float* __restrict__ Wout) {
    int i = blockIdx.x * blockDim.x + threadIdx.x;
    if (i < 257 * 256) {
        int r = i >> 8, c = i & 255;
        if (r < 256) {
            float z = (r == c) ? 0.0f : 1.0f;
            g_V1[i]  = V1[r * 256 + c] * z;
            g_V2[i]  = V2[r * 256 + c] * z;
            g_W2T[i] = W2[c * 256 + r];
        } else {
            g_V1[i] = 0.f; g_V2[i] = 0.f; g_W2T[i] = 0.f;
        }
    }
    if (i < 257 * 200) {
        int h = i / 200, o = i - h * 200;
        g_WoT[i] = (h < 256) ? Wout[o * 256 + h] : 0.f;
    }
}

// Dynamic SMEM layout (float index):
#define OFF_W1T  0        // [5120]  W1 transposed [F][H]
#define OFF_PA   5120     // [4*256] V1  partials
#define OFF_PC   6144     // [4*256] W2T partials
#define OFF_PB   7168     // [4*256] V2  partials
#define OFF_PW   8192     // [4*256] WoT partials
#define OFF_L1   9216     // [2*260] int: ping-pong padded spike list layer1
#define OFF_L2   9736     // [2*260] int: ping-pong padded spike list layer2
#define OFF_WC1  10256    // [8]   int
#define OFF_WC2  10264    // [8]   int
#define OFF_NCNT 10272    // [4]   int: n1[2], n2[2]
#define OFF_XBUF 10276    // [2*20] x(t) double buffer
#define SMEM_FLOATS (10276 + 40)
#define SMEM_BYTES  (SMEM_FLOATS * 4)

#define NB1() asm volatile("bar.sync 1, 256;" ::: "memory")   // warps 0-7   (layer1)
#define NB2() asm volatile("bar.sync 3, 256;" ::: "memory")   // warps 8-15  (layer2)
#define ADDX2(d, a, b) asm("add.rn.f32x2 %0, %1, %2;" : "=l"(d) : "l"(a), "l"(b))

// Gather 4 consecutive ids (one int4 block) from `base` rows of `stride` floats.
#define GATHER4(ptr, stride)                                                    \
    do {                                                                        \
        ulonglong2 v0 = __ldg((const ulonglong2*)((ptr) + e.x * (stride)));     \
        ulonglong2 v1 = __ldg((const ulonglong2*)((ptr) + e.y * (stride)));     \
        ulonglong2 v2 = __ldg((const ulonglong2*)((ptr) + e.z * (stride)));     \
        ulonglong2 v3 = __ldg((const ulonglong2*)((ptr) + e.w * (stride)));     \
        ADDX2(s0, s0, v0.x); ADDX2(s1, s1, v0.y);                               \
        ADDX2(s2, s2, v1.x); ADDX2(s3, s3, v1.y);                               \
        ADDX2(s0, s0, v2.x); ADDX2(s1, s1, v2.y);                               \
        ADDX2(s2, s2, v3.x); ADDX2(s3, s3, v3.y);                               \
    } while (0)

__global__ __launch_bounds__(NTHR, 1)
void snn_main(const float* __restrict__ x, const float* __restrict__ W1,
              const float* __restrict__ b1, const float* __restrict__ beta1,
              const float* __restrict__ b2, const float* __restrict__ beta2,
              const float* __restrict__ alpha_out, const float* __restrict__ beta_out) {
    extern __shared__ float sm[];
    float* w1t  = sm + OFF_W1T;
    float* PA   = sm + OFF_PA;
    float* PC   = sm + OFF_PC;
    float* PB   = sm + OFF_PB;
    float* PW   = sm + OFF_PW;
    int*   l1   = (int*)(sm + OFF_L1);
    int*   l2   = (int*)(sm + OFF_L2);
    int*   wc1  = (int*)(sm + OFF_WC1);
    int*   wc2  = (int*)(sm + OFF_WC2);
    int*   ncnt = (int*)(sm + OFF_NCNT);
    float* xbuf = sm + OFF_XBUF;

    const int tid  = threadIdx.x;
    const int b    = blockIdx.x;
    const int grp  = tid >> 6;              // 0..15 (64-thread row groups)
    const int g    = grp & 3;               // group within matrix
    const int mat  = grp >> 2;              // 0:V1 1:W2T 2:V2 3:WoT
    const int lg   = tid & 63;              // float4 column within row
    const int wid  = tid >> 5, lane = tid & 31;
    const float* xb = x + (size_t)b * (Tt * Ft);

    for (int i = tid; i < Ft * Ht; i += NTHR) {       // W1^T [F][H]
        int f = i >> 8, h = i & 255;
        w1t[i] = W1[h * Ft + f];
    }
    if (tid < 4) ncnt[tid] = 0;
    if (tid < Ft) xbuf[tid] = __ldg(xb + tid);        // x(0) -> slot 0

    // Role state: layer1 on tid 0-255, layer2 on 256-511, readout on 768-967
    // (the WoT gather band itself -> PW producer == consumer).
    float syn1 = 0.f, mem1 = 0.f, spk1 = 0.f;
    float syn2 = 0.f, mem2 = 0.f, spk2 = 0.f;
    float synO = 0.f, memO = 0.f, spkO = 0.f;
    float b1r = 0.f, be1 = 0.f, b2r = 0.f, be2 = 0.f, aOr = 0.f, bOr = 0.f;
    const int h2 = tid - 256;                         // layer2 neuron index
    const int oo = tid - 768;                         // output neuron index (band 3)
    if (tid < Ht)              { b1r = b1[tid]; be1 = beta1[tid]; }
    if (h2 >= 0 && h2 < Ht)    { b2r = b2[h2];  be2 = beta2[h2]; }
    if (oo >= 0 && oo < Ot)    { aOr = alpha_out[oo]; bOr = beta_out[oo]; }
    __syncthreads();

    // Iteration t: layer1 step t (t<Tt), layer2 step t-1 (1<=t<=Tt),
    // readout step t-2 (2<=t<=Tt+1). Gathers read parity q, updates write p.
    for (int t = 0; t <= Tt + 1; t++) {
        const int p = t & 1, q = p ^ 1;
        const int nB1o = (ncnt[q] + 3) >> 2;      // int4 blocks in l1[q]
        const int nB2o = (ncnt[2 + q] + 3) >> 2;  // int4 blocks in l2[q]

        float xnext = 0.f;
        if (tid < Ft && t + 1 < Tt) xnext = __ldg(xb + (t + 1) * Ft + tid);

        // ---- single gather phase: 4 matrices concurrently, int4 list blocks ----
        if (mat == 0) {               // V1 rows over l1[q] -> PA
            if (t < Tt) {
                const float* base = g_V1 + 4 * lg;
                const int4* lst4 = (const int4*)(l1 + q * 260);
                unsigned long long s0 = 0ull, s1 = 0ull, s2 = 0ull, s3 = 0ull;
                #pragma unroll 2
                for (int k = g; k < nB1o; k += 4) {
                    int4 e = lst4[k];
                    GATHER4(base, 256);
                }
                ulonglong2 r; ADDX2(r.x, s0, s2); ADDX2(r.y, s1, s3);
                *(ulonglong2*)(PA + g * 256 + 4 * lg) = r;
            }
        } else if (mat == 1) {        // W2T rows over l1[q] -> PC
            if (t >= 1 && t <= Tt) {
                const float* base = g_W2T + 4 * lg;
                const int4* lst4 = (const int4*)(l1 + q * 260);
                unsigned long long s0 = 0ull, s1 = 0ull, s2 = 0ull, s3 = 0ull;
                #pragma unroll 2
                for (int k = g; k < nB1o; k += 4) {
                    int4 e = lst4[k];
                    GATHER4(base, 256);
                }
                ulonglong2 r; ADDX2(r.x, s0, s2); ADDX2(r.y, s1, s3);
                *(ulonglong2*)(PC + g * 256 + 4 * lg) = r;
            }
        } else if (mat == 2) {        // V2 rows over l2[q] -> PB
            if (t >= 1 && t <= Tt) {
                const float* base = g_V2 + 4 * lg;
                const int4* lst4 = (const int4*)(l2 + q * 260);
                unsigned long long s0 = 0ull, s1 = 0ull, s2 = 0ull, s3 = 0ull;
                #pragma unroll 2
                for (int k = g; k < nB2o; k += 4) {
                    int4 e = lst4[k];
                    GATHER4(base, 256);
                }
                ulonglong2 r; ADDX2(r.x, s0, s2); ADDX2(r.y, s1, s3);
                *(ulonglong2*)(PB + g * 256 + 4 * lg) = r;
            }
        } else {                      // WoT rows (200 wide) over l2[q] -> PW
            if (t >= 2 && lg < 50) {
                const float* base = g_WoT + 4 * lg;
                const int4* lst4 = (const int4*)(l2 + q * 260);
                unsigned long long s0 = 0ull, s1 = 0ull, s2 = 0ull, s3 = 0ull;
                #pragma unroll 2
                for (int k = g; k < nB2o; k += 4) {
                    int4 e = lst4[k];
                    GATHER4(base, 200);
                }
                ulonglong2 r; ADDX2(r.x, s0, s2); ADDX2(r.y, s1, s3);
                *(ulonglong2*)(PW + g * 256 + 4 * lg) = r;
            }
        }
        __syncthreads();                                        // S1
        if (tid < Ft && t + 1 < Tt) xbuf[q * Ft + tid] = xnext;

        // ---- layer1 step t (warps 0-7) ----
        if (t < Tt && tid < Ht) {
            const float* xt = xbuf + p * Ft;
            float a0 = b1r, a1 = 0.f, a2 = 0.f, a3 = 0.f;
            #pragma unroll
            for (int f = 0; f < 5; f++) {
                a0 = fmaf(xt[f],      w1t[f * Ht + tid],        a0);
                a1 = fmaf(xt[f + 5],  w1t[(f + 5) * Ht + tid],  a1);
                a2 = fmaf(xt[f + 10], w1t[(f + 10) * Ht + tid], a2);
                a3 = fmaf(xt[f + 15], w1t[(f + 15) * Ht + tid], a3);
            }
            float wx = (a0 + a1) + (a2 + a3);
            float s = ((PA[tid] + PA[256 + tid]) + (PA[512 + tid] + PA[768 + tid]));
            syn1 = 0.95f * syn1 + (wx + s);
            mem1 = be1 * mem1 + syn1 - spk1;                    // THR=1, detached reset
            spk1 = (mem1 - 1.0f) > 0.f ? 1.f : 0.f;

            unsigned bal = __ballot_sync(0xffffffffu, spk1 != 0.f);
            if (lane == 0) wc1[wid] = __popc(bal);
            NB1();
            int off = 0, tot = 0;
            #pragma unroll
            for (int w = 0; w < 8; w++) { int c = wc1[w]; off += (w < wid) ? c : 0; tot += c; }
            if (spk1 != 0.f) l1[p * 260 + off + __popc(bal & ((1u << lane) - 1u))] = tid;
            if (tid >= tot && tid < tot + 4) l1[p * 260 + tid] = ZID;  // pad block
            if (tid == 0) ncnt[p] = tot;
        }

        // ---- layer2 step t-1 (warps 8-15) ----
        if (t >= 1 && t <= Tt && h2 >= 0 && h2 < Ht) {
            const int w2 = wid - 8;
            float s = ((PC[h2] + PC[256 + h2]) + (PC[512 + h2] + PC[768 + h2])) +
                      ((PB[h2] + PB[256 + h2]) + (PB[512 + h2] + PB[768 + h2]));
            syn2 = 0.95f * syn2 + (b2r + s);
            mem2 = be2 * mem2 + syn2 - spk2;
            spk2 = (mem2 - 1.0f) > 0.f ? 1.f : 0.f;

            unsigned bal = __ballot_sync(0xffffffffu, spk2 != 0.f);
            if (lane == 0) wc2[w2] = __popc(bal);
            NB2();
            int off = 0, tot = 0;
            #pragma unroll
            for (int w = 0; w < 8; w++) { int c = wc2[w]; off += (w < w2) ? c : 0; tot += c; }
            if (spk2 != 0.f) l2[p * 260 + off + __popc(bal & ((1u << lane) - 1u))] = h2;
            if (h2 >= tot && h2 < tot + 4) l2[p * 260 + h2] = ZID;    // pad block
            if (h2 == 0) ncnt[2 + p] = tot;
        }

        // ---- readout step t-2 (band 3, warps 24-31): state update + stream memO ----
        if (t >= 2 && oo >= 0 && oo < Ot) {
            float o_t = ((PW[oo] + PW[256 + oo]) + (PW[512 + oo] + PW[768 + oo]));
            synO = aOr * synO + o_t;
            memO = bOr * memO + synO - spkO;
            spkO = (memO - 1.0f) > 0.f ? 1.f : 0.f;
            g_memO[((size_t)(t - 2) * Bt + b) * Ot + oo] = memO;
        }
        __syncthreads();                                        // S2
    }
}

// out zeroing (d_out poisoned by harness).
__global__ __launch_bounds__(256) void snn_zero(float* __restrict__ out) {
    int i = blockIdx.x * blockDim.x + threadIdx.x;
    if (i < Bt * Ot) out[i] = 0.f;
}

// Deferred softmax, warp-per-(b, 25-step chunk). No block barriers; the 200-wide
// softmax lives in one warp: 7 coalesced loads/lane, 5-shfl max, 5-shfl sum.
#define CHUNK 25
#define NCHUNK (Tt / CHUNK)     // 40
__global__ __launch_bounds__(256) void snn_soft(float* __restrict__ out) {
    const int gw = blockIdx.x * 8 + (threadIdx.x >> 5);   // global warp id
    const int ln = threadIdx.x & 31;
    const int bb = gw / NCHUNK, ch = gw - bb * NCHUNK;
    if (bb >= Bt) return;
    int t0 = ch * CHUNK; if (t0 < 11) t0 = 11;            // step > WARMUP(10)
    const int t1 = (ch + 1) * CHUNK;

    float acc[7] = {0.f, 0.f, 0.f, 0.f, 0.f, 0.f, 0.f};
    for (int tau = t0; tau < t1; tau++) {
        const float* row = g_memO + ((size_t)tau * Bt + bb) * Ot;
        float m[7], mv = -3.402823e38f;
        #pragma unroll
        for (int k = 0; k < 7; k++) {
            int o = ln + 32 * k;
            m[k] = (o < Ot) ? __ldg(row + o) : -3.402823e38f;
            mv = fmaxf(mv, m[k]);
        }
        #pragma unroll
        for (int s = 16; s; s >>= 1) mv = fmaxf(mv, __shfl_xor_sync(0xffffffffu, mv, s));
        float ev[7], sv = 0.f;
        #pragma unroll
        for (int k = 0; k < 7; k++) {
            ev[k] = __expf(m[k] - mv);        // exp(-huge) = 0 for padding lanes
            sv += ev[k];
        }
        #pragma unroll
        for (int s = 16; s; s >>= 1) sv += __shfl_xor_sync(0xffffffffu, sv, s);
        float inv = __frcp_rn(sv);
        #pragma unroll
        for (int k = 0; k < 7; k++) acc[k] = fmaf(ev[k], inv, acc[k]);
    }
    #pragma unroll
    for (int k = 0; k < 7; k++) {
        int o = ln + 32 * k;
        if (o < Ot) atomicAdd(&out[bb * Ot + o], acc[k]);
    }
}

extern "C" void kernel_launch(void* const* d_in, const int* in_sizes, int n_in,
                              void* d_out, int out_size) {
    const float* x         = (const float*)d_in[0];
    const float* W1        = (const float*)d_in[1];
    const float* b1        = (const float*)d_in[2];
    const float* Vrec1     = (const float*)d_in[3];
    const float* beta1     = (const float*)d_in[4];
    const float* W2        = (const float*)d_in[5];
    const float* b2        = (const float*)d_in[6];
    const float* Vrec2     = (const float*)d_in[7];
    const float* beta2     = (const float*)d_in[8];
    const float* Wout      = (const float*)d_in[9];
    const float* alpha_out = (const float*)d_in[10];
    const float* beta_out  = (const float*)d_in[11];
    float* out = (float*)d_out;

    cudaFuncSetAttribute((const void*)snn_main,
                         cudaFuncAttributeMaxDynamicSharedMemorySize, SMEM_BYTES);

    snn_prep<<<(257 * 256 + 255) / 256, 256>>>(Vrec1, Vrec2, W2, Wout);
    snn_main<<<Bt, NTHR, SMEM_BYTES>>>(x, W1, b1, beta1, b2, beta2,
                                       alpha_out, beta_out);
    snn_zero<<<(Bt * Ot + 255) / 256, 256>>>(out);
    snn_soft<<<(Bt * NCHUNK + 7) / 8, 256>>>(out);
}

// round 13
// speedup vs baseline: 1.0947x; 1.0518x over previous
#include <cuda_runtime.h>

// SNN forward: B=128, T=1000, F=20, H=256, O=200.
// snn_main: 1 CTA per batch element, 1024 threads, layer-pipelined.
// R13: CTA split into two decoupled 512-thread macro-bands:
//   Band A (warps 0-15):  V1+W2T gathers, layer1 update (step t), layer2 update
//                         (step t-1), publishes spike lists l1/l2.
//   Band B (warps 16-31): V2+WoT gathers (over lists from previous A iteration,
//                         phase-offset barrier), readout state (step t-2) + memO.
// Cross-band sync via named barriers (no full __syncthreads in the loop):
//   id6 "l2-ready" (A arrives end of iter, B syncs at top; prologue arrive)
//   id5 "PB-ready" (B arrives post-gather, A's update2 half syncs)
// B's gathers overlap A's update window -> L2 queues stay fed.

#define Bt 128
#define Tt 1000
#define Ft 20
#define Ht 256
#define Ot 200
#define NTHR 1024
#define ZID 256                 // id of the all-zero padding row

__device__ __align__(16) float g_V1[257 * 256];
__device__ __align__(16) float g_V2[257 * 256];
__device__ __align__(16) float g_W2T[257 * 256];   // W2T[h][g] = W2[g][h]
__device__ __align__(16) float g_WoT[257 * 200];   // WoT[h][o] = Wout[o][h]
__device__ float g_memO[(size_t)Tt * Bt * Ot];     // memO series for deferred softmax

__global__ void snn_prep(const float* __restrict__ V1, const float* __restrict__ V2,
                         const float* __restrict__ W2, const float* __restrict__ Wout) {
    int i = blockIdx.x * blockDim.x + threadIdx.x;
    if (i < 257 * 256) {
        int r = i >> 8, c = i & 255;
        if (r < 256) {
            float z = (r == c) ? 0.0f : 1.0f;
            g_V1[i]  = V1[r * 256 + c] * z;
            g_V2[i]  = V2[r * 256 + c] * z;
            g_W2T[i] = W2[c * 256 + r];
        } else {
            g_V1[i] = 0.f; g_V2[i] = 0.f; g_W2T[i] = 0.f;
        }
    }
    if (i < 257 * 200) {
        int h = i / 200, o = i - h * 200;
        g_WoT[i] = (h < 256) ? Wout[o * 256 + h] : 0.f;
    }
}

// Dynamic SMEM layout (float index):
#define OFF_W1T  0        // [5120]  W1 transposed [F][H]
#define OFF_PA   5120     // [4*256] V1  partials (A-internal)
#define OFF_PC   6144     // [4*256] W2T partials (A-internal)
#define OFF_PB   7168     // [4*256] V2  partials (B -> A, id7+id5 ordered)
#define OFF_PW   8192     // [4*256] WoT partials (B-internal)
#define OFF_L1   9216     // [2*260] int: ping-pong padded spike list layer1
#define OFF_L2   9736     // [2*260] int: ping-pong padded spike list layer2
#define OFF_WC1  10256    // [8]   int
#define OFF_WC2  10264    // [8]   int
#define OFF_NCNT 10272    // [4]   int: n1[2], n2[2]
#define OFF_XBUF 10276    // [2*20] x(t) double buffer
#define SMEM_FLOATS (10276 + 40)
#define SMEM_BYTES  (SMEM_FLOATS * 4)

#define BSYNC(id, n)   asm volatile("bar.sync %0, %1;"   :: "r"(id), "r"(n) : "memory")
#define BARRIVE(id, n) asm volatile("bar.arrive %0, %1;" :: "r"(id), "r"(n) : "memory")
#define ADDX2(d, a, b) asm("add.rn.f32x2 %0, %1, %2;" : "=l"(d) : "l"(a), "l"(b))

// Gather 4 consecutive ids (one int4 block) from `ptr` rows of `stride` floats.
#define GATHER4(ptr, stride)                                                    \
    do {                                                                        \
        ulonglong2 v0 = __ldg((const ulonglong2*)((ptr) + e.x * (stride)));     \
        ulonglong2 v1 = __ldg((const ulonglong2*)((ptr) + e.y * (stride)));     \
        ulonglong2 v2 = __ldg((const ulonglong2*)((ptr) + e.z * (stride)));     \
        ulonglong2 v3 = __ldg((const ulonglong2*)((ptr) + e.w * (stride)));     \
        ADDX2(s0, s0, v0.x); ADDX2(s1, s1, v0.y);                               \
        ADDX2(s2, s2, v1.x); ADDX2(s3, s3, v1.y);                               \
        ADDX2(s0, s0, v2.x); ADDX2(s1, s1, v2.y);                               \
        ADDX2(s2, s2, v3.x); ADDX2(s3, s3, v3.y);                               \
    } while (0)

__global__ __launch_bounds__(NTHR, 1)
void snn_main(const float* __restrict__ x, const float* __restrict__ W1,
              const float* __restrict__ b1, const float* __restrict__ beta1,
              const float* __restrict__ b2, const float* __restrict__ beta2,
              const float* __restrict__ alpha_out, const float* __restrict__ beta_out) {
    extern __shared__ float sm[];
    float* w1t  = sm + OFF_W1T;
    float* PA   = sm + OFF_PA;
    float* PC   = sm + OFF_PC;
    float* PB   = sm + OFF_PB;
    float* PW   = sm + OFF_PW;
    int*   l1   = (int*)(sm + OFF_L1);
    int*   l2   = (int*)(sm + OFF_L2);
    int*   wc1  = (int*)(sm + OFF_WC1);
    int*   wc2  = (int*)(sm + OFF_WC2);
    int*   ncnt = (int*)(sm + OFF_NCNT);
    float* xbuf = sm + OFF_XBUF;

    const int tid  = threadIdx.x;
    const int b    = blockIdx.x;
    const int lg   = tid & 63;              // float4 column within row
    const int wid  = tid >> 5, lane = tid & 31;
    const float* xb = x + (size_t)b * (Tt * Ft);

    for (int i = tid; i < Ft * Ht; i += NTHR) {       // W1^T [F][H]
        int f = i >> 8, h = i & 255;
        w1t[i] = W1[h * Ft + f];
    }
    if (tid < 4) ncnt[tid] = 0;
    if (tid < Ft) xbuf[tid] = __ldg(xb + tid);        // x(0) -> slot 0

    float syn1 = 0.f, mem1 = 0.f, spk1 = 0.f;
    float syn2 = 0.f, mem2 = 0.f, spk2 = 0.f;
    float synO = 0.f, memO = 0.f, spkO = 0.f;
    float b1r = 0.f, be1 = 0.f, b2r = 0.f, be2 = 0.f, aOr = 0.f, bOr = 0.f;
    const int h2 = tid - 256;                         // layer2 neuron index (A upper half)
    const int oo = tid - 768;                         // output neuron index (B)
    if (tid < Ht)              { b1r = b1[tid]; be1 = beta1[tid]; }
    if (h2 >= 0 && h2 < Ht)    { b2r = b2[h2];  be2 = beta2[h2]; }
    if (oo >= 0 && oo < Ot)    { aOr = alpha_out[oo]; bOr = beta_out[oo]; }
    __syncthreads();
    // Prologue arrive for the phase-offset l2-ready barrier (iteration "-1").
    if (tid >= 256 && tid < 512) BARRIVE(6, 768);

    for (int t = 0; t <= Tt + 1; t++) {
        const int p = t & 1, q = p ^ 1;

        if (tid < 512) {
            // ================= BAND A =================
            const int grp = tid >> 6;                 // 0-3: V1, 4-7: W2T
            const int nB1o = (ncnt[q] + 3) >> 2;      // int4 blocks in l1[q]

            float xnext = 0.f;
            if (tid < Ft && t + 1 < Tt) xnext = __ldg(xb + (t + 1) * Ft + tid);

            if (grp < 4) {            // V1 rows over l1[q] -> PA
                if (t < Tt) {
                    const int g = grp;
                    const float* base = g_V1 + 4 * lg;
                    const int4* lst4 = (const int4*)(l1 + q * 260);
                    unsigned long long s0 = 0ull, s1 = 0ull, s2 = 0ull, s3 = 0ull;
                    #pragma unroll 2
                    for (int k = g; k < nB1o; k += 4) {
                        int4 e = lst4[k];
                        GATHER4(base, 256);
                    }
                    ulonglong2 r; ADDX2(r.x, s0, s2); ADDX2(r.y, s1, s3);
                    *(ulonglong2*)(PA + g * 256 + 4 * lg) = r;
                }
            } else {                  // W2T rows over l1[q] -> PC
                if (t >= 1 && t <= Tt) {
                    const int g = grp - 4;
                    const float* base = g_W2T + 4 * lg;
                    const int4* lst4 = (const int4*)(l1 + q * 260);
                    unsigned long long s0 = 0ull, s1 = 0ull, s2 = 0ull, s3 = 0ull;
                    #pragma unroll 2
                    for (int k = g; k < nB1o; k += 4) {
                        int4 e = lst4[k];
                        GATHER4(base, 256);
                    }
                    ulonglong2 r; ADDX2(r.x, s0, s2); ADDX2(r.y, s1, s3);
                    *(ulonglong2*)(PC + g * 256 + 4 * lg) = r;
                }
            }
            BSYNC(4, 512);                            // PA/PC visible within A
            if (tid < Ft && t + 1 < Tt) xbuf[q * Ft + tid] = xnext;

            if (tid < 256) {
                // ---- layer1 step t ----
                if (t < Tt) {
                    const float* xt = xbuf + p * Ft;
                    float a0 = b1r, a1 = 0.f, a2 = 0.f, a3 = 0.f;
                    #pragma unroll
                    for (int f = 0; f < 5; f++) {
                        a0 = fmaf(xt[f],      w1t[f * Ht + tid],        a0);
                        a1 = fmaf(xt[f + 5],  w1t[(f + 5) * Ht + tid],  a1);
                        a2 = fmaf(xt[f + 10], w1t[(f + 10) * Ht + tid], a2);
                        a3 = fmaf(xt[f + 15], w1t[(f + 15) * Ht + tid], a3);
                    }
                    float wx = (a0 + a1) + (a2 + a3);
                    float s = ((PA[tid] + PA[256 + tid]) + (PA[512 + tid] + PA[768 + tid]));
                    syn1 = 0.95f * syn1 + (wx + s);
                    mem1 = be1 * mem1 + syn1 - spk1;  // THR=1, detached reset
                    spk1 = (mem1 - 1.0f) > 0.f ? 1.f : 0.f;

                    unsigned bal = __ballot_sync(0xffffffffu, spk1 != 0.f);
                    if (lane == 0) wc1[wid] = __popc(bal);
                    BSYNC(1, 256);
                    int off = 0, tot = 0;
                    #pragma unroll
                    for (int w = 0; w < 8; w++) { int c = wc1[w]; off += (w < wid) ? c : 0; tot += c; }
                    if (spk1 != 0.f) l1[p * 260 + off + __popc(bal & ((1u << lane) - 1u))] = tid;
                    if (tid >= tot && tid < tot + 4) l1[p * 260 + tid] = ZID;
                    if (tid == 0) ncnt[p] = tot;
                }
            } else {
                BSYNC(5, 768);                        // wait PB (B's V2 gather, this iter)
                // ---- layer2 step t-1 ----
                if (t >= 1 && t <= Tt) {
                    const int w2 = wid - 8;
                    float s = ((PC[h2] + PC[256 + h2]) + (PC[512 + h2] + PC[768 + h2])) +
                              ((PB[h2] + PB[256 + h2]) + (PB[512 + h2] + PB[768 + h2]));
                    syn2 = 0.95f * syn2 + (b2r + s);
                    mem2 = be2 * mem2 + syn2 - spk2;
                    spk2 = (mem2 - 1.0f) > 0.f ? 1.f : 0.f;

                    unsigned bal = __ballot_sync(0xffffffffu, spk2 != 0.f);
                    if (lane == 0) wc2[w2] = __popc(bal);
                    BSYNC(3, 256);
                    int off = 0, tot = 0;
                    #pragma unroll
                    for (int w = 0; w < 8; w++) { int c = wc2[w]; off += (w < w2) ? c : 0; tot += c; }
                    if (spk2 != 0.f) l2[p * 260 + off + __popc(bal & ((1u << lane) - 1u))] = h2;
                    if (h2 >= tot && h2 < tot + 4) l2[p * 260 + h2] = ZID;
                    if (h2 == 0) ncnt[2 + p] = tot;
                }
            }
            BSYNC(8, 512);                            // lists + ncnt published within A
            if (tid >= 256) BARRIVE(6, 768);          // l2-ready for B's NEXT sync
        } else {
            // ================= BAND B =================
            BSYNC(6, 768);                            // l2[q]/ncnt ready (A, prev iter)
            const int grp = (tid - 512) >> 6;         // 0-3: V2, 4-7: WoT
            const int nB2o = (ncnt[2 + q] + 3) >> 2;  // int4 blocks in l2[q]

            if (grp < 4) {            // V2 rows over l2[q] -> PB
                if (t >= 1 && t <= Tt) {
                    const int g = grp;
                    const float* base = g_V2 + 4 * lg;
                    const int4* lst4 = (const int4*)(l2 + q * 260);
                    unsigned long long s0 = 0ull, s1 = 0ull, s2 = 0ull, s3 = 0ull;
                    #pragma unroll 2
                    for (int k = g; k < nB2o; k += 4) {
                        int4 e = lst4[k];
                        GATHER4(base, 256);
                    }
                    ulonglong2 r; ADDX2(r.x, s0, s2); ADDX2(r.y, s1, s3);
                    *(ulonglong2*)(PB + g * 256 + 4 * lg) = r;
                }
            } else {                  // WoT rows (200 wide) over l2[q] -> PW
                if (t >= 2 && lg < 50) {
                    const int g = grp - 4;
                    const float* base = g_WoT + 4 * lg;
                    const int4* lst4 = (const int4*)(l2 + q * 260);
                    unsigned long long s0 = 0ull, s1 = 0ull, s2 = 0ull, s3 = 0ull;
                    #pragma unroll 2
                    for (int k = g; k < nB2o; k += 4) {
                        int4 e = lst4[k];
                        GATHER4(base, 200);
                    }
                    ulonglong2 r; ADDX2(r.x, s0, s2); ADDX2(r.y, s1, s3);
                    *(ulonglong2*)(PW + g * 256 + 4 * lg) = r;
                }
            }
            BSYNC(7, 512);                            // PB/PW visible (B-internal)
            BARRIVE(5, 768);                          // PB-ready for A's update2

            // ---- readout step t-2: state update + stream memO ----
            if (t >= 2 && oo >= 0 && oo < Ot) {
                float o_t = ((PW[oo] + PW[256 + oo]) + (PW[512 + oo] + PW[768 + oo]));
                synO = aOr * synO + o_t;
                memO = bOr * memO + synO - spkO;
                spkO = (memO - 1.0f) > 0.f ? 1.f : 0.f;
                g_memO[((size_t)(t - 2) * Bt + b) * Ot + oo] = memO;
            }
        }
    }
}

// out zeroing (d_out poisoned by harness).
__global__ __launch_bounds__(256) void snn_zero(float* __restrict__ out) {
    int i = blockIdx.x * blockDim.x + threadIdx.x;
    if (i < Bt * Ot) out[i] = 0.f;
}

// Deferred softmax, warp-per-(b, 25-step chunk).
#define CHUNK 25
#define NCHUNK (Tt / CHUNK)     // 40
__global__ __launch_bounds__(256) void snn_soft(float* __restrict__ out) {
    const int gw = blockIdx.x * 8 + (threadIdx.x >> 5);
    const int ln = threadIdx.x & 31;
    const int bb = gw / NCHUNK, ch = gw - bb * NCHUNK;
    if (bb >= Bt) return;
    int t0 = ch * CHUNK; if (t0 < 11) t0 = 11;            // step > WARMUP(10)
    const int t1 = (ch + 1) * CHUNK;

    float acc[7] = {0.f, 0.f, 0.f, 0.f, 0.f, 0.f, 0.f};
    for (int tau = t0; tau < t1; tau++) {
        const float* row = g_memO + ((size_t)tau * Bt + bb) * Ot;
        float m[7], mv = -3.402823e38f;
        #pragma unroll
        for (int k = 0; k < 7; k++) {
            int o = ln + 32 * k;
            m[k] = (o < Ot) ? __ldg(row + o) : -3.402823e38f;
            mv = fmaxf(mv, m[k]);
        }
        #pragma unroll
        for (int s = 16; s; s >>= 1) mv = fmaxf(mv, __shfl_xor_sync(0xffffffffu, mv, s));
        float ev[7], sv = 0.f;
        #pragma unroll
        for (int k = 0; k < 7; k++) { ev[k] = __expf(m[k] - mv); sv += ev[k]; }
        #pragma unroll
        for (int s = 16; s; s >>= 1) sv += __shfl_xor_sync(0xffffffffu, sv, s);
        float inv = __frcp_rn(sv);
        #pragma unroll
        for (int k = 0; k < 7; k++) acc[k] = fmaf(ev[k], inv, acc[k]);
    }
    #pragma unroll
    for (int k = 0; k < 7; k++) {
        int o = ln + 32 * k;
        if (o < Ot) atomicAdd(&out[bb * Ot + o], acc[k]);
    }
}

extern "C" void kernel_launch(void* const* d_in, const int* in_sizes, int n_in,
                              void* d_out, int out_size) {
    const float* x         = (const float*)d_in[0];
    const float* W1        = (const float*)d_in[1];
    const float* b1        = (const float*)d_in[2];
    const float* Vrec1     = (const float*)d_in[3];
    const float* beta1     = (const float*)d_in[4];
    const float* W2        = (const float*)d_in[5];
    const float* b2        = (const float*)d_in[6];
    const float* Vrec2     = (const float*)d_in[7];
    const float* beta2     = (const float*)d_in[8];
    const float* Wout      = (const float*)d_in[9];
    const float* alpha_out = (const float*)d_in[10];
    const float* beta_out  = (const float*)d_in[11];
    float* out = (float*)d_out;

    cudaFuncSetAttribute((const void*)snn_main,
                         cudaFuncAttributeMaxDynamicSharedMemorySize, SMEM_BYTES);

    snn_prep<<<(257 * 256 + 255) / 256, 256>>>(Vrec1, Vrec2, W2, Wout);
    snn_main<<<Bt, NTHR, SMEM_BYTES>>>(x, W1, b1, beta1, b2, beta2,
                                       alpha_out, beta_out);
    snn_zero<<<(Bt * Ot + 255) / 256, 256>>>(out);
    snn_soft<<<(Bt * NCHUNK + 7) / 8, 256>>>(out);
}